// round 11
// baseline (speedup 1.0000x reference)
#include <cuda_runtime.h>
#include <cstdint>

#define Bq 64
#define Tq 512
#define Dq 1024
#define Mq (Bq*Tq)

// ---- scratch (device globals: allocation-free) ----
__device__ float g_xtau[Tq*Bq*Dq];   // [t][b][d]
__device__ float g_mem [Tq*Bq*Dq];   // [t][b][d]
__device__ float g_tauT[2*Dq*Bq];    // ping-pong, TRANSPOSED [p][d][b]
__device__ float g_v   [Dq*Bq];      // TRANSPOSED [d][b]

typedef unsigned long long ull;

__device__ __forceinline__ ull pk2(float lo, float hi) {
    ull r; asm("mov.b64 %0, {%1,%2};" : "=l"(r) : "f"(lo), "f"(hi)); return r;
}
__device__ __forceinline__ void upk2(ull a, float& lo, float& hi) {
    asm("mov.b64 {%0,%1}, %2;" : "=f"(lo), "=f"(hi) : "l"(a));
}
__device__ __forceinline__ ull fma2(ull a, ull b, ull c) {
    ull d; asm("fma.rn.f32x2 %0, %1, %2, %3;" : "=l"(d) : "l"(a), "l"(b), "l"(c)); return d;
}
__device__ __forceinline__ ull add2(ull a, ull b) {
    ull d; asm("add.rn.f32x2 %0, %1, %2;" : "=l"(d) : "l"(a), "l"(b)); return d;
}
__device__ __forceinline__ float sigm(float x) { return 1.0f / (1.0f + expf(-x)); }

__device__ __forceinline__ uint32_t su32(const void* p) {
    uint32_t a;
    asm("{ .reg .u64 t; cvta.to.shared.u64 t, %1; cvt.u32.u64 %0, t; }"
        : "=r"(a) : "l"(p));
    return a;
}
__device__ __forceinline__ void cpa16(uint32_t dst, const void* src) {
    asm volatile("cp.async.cg.shared.global [%0], [%1], 16;" :: "r"(dst), "l"(src));
}
#define CPA_COMMIT() asm volatile("cp.async.commit_group;")
#define CPA_WAIT2()  asm volatile("cp.async.wait_group 2;")

// ---- dynamic smem layout (byte offsets) ----
#define OFF_W    0                     // 32KB  weights [k][4 ull colpairs]
#define OFF_TAU  32768                 // 4 x 32KB tau chunk ring
#define OFF_X    (32768 + 131072)      // 2KB  xtau rows [b][8]
#define OFF_M    (OFF_X + 2048)        // 2KB  mem rows  [b][8]
#define OFF_V    (OFF_M + 2048)        // 2KB  v [j][64]
#define OFF_DOT  (OFF_V + 2048)        // 2KB  reduced dots [b][8]
#define OFF_LT   (OFF_DOT + 2048)      // 64B  log_thresh slice
#define SMEM_BYTES (OFF_LT + 64)       // 172096

// ============================================================
// Init: tau ping buffer = 1, v = 0, thresh output
// ============================================================
__global__ void init_kernel(const float* __restrict__ log_thresh,
                            float* __restrict__ out)
{
    int i = blockIdx.x * blockDim.x + threadIdx.x;
    if (i < Dq * Bq) {
        g_tauT[i] = 1.0f;
        g_v[i]    = 0.0f;
    }
    if (i < Dq)
        out[(size_t)Mq * Dq + 2 * Bq * Dq + i] = sigm(log_thresh[i]);
}

// ============================================================
// Phase 1: big GEMMs (at FFMA2 issue floor; unchanged)
// ============================================================
__global__ __launch_bounds__(256, 1) void gemm_kernel(
    const float* __restrict__ x,
    const float* __restrict__ Wt, const float* __restrict__ bt,
    const float* __restrict__ Wm, const float* __restrict__ bm)
{
    const int z = blockIdx.z;
    const float* __restrict__ W    = z ? Wm : Wt;
    const float* __restrict__ bias = z ? bm : bt;
    float* __restrict__ out        = z ? g_mem : g_xtau;

    __shared__ ull As2[8 * 128];
    __shared__ ull Bs2[8 * 64];

    const int tid = threadIdx.x;
    const int tx = tid & 15, ty = tid >> 4;
    const int m0 = blockIdx.y * 128;
    const int n0 = blockIdx.x * 128;

    const int ar  = tid >> 1;
    const int kc  = (tid & 1) * 4;
    const int brk = tid >> 5;
    const int bc  = tid & 31;

    ull acc[8][4];
#pragma unroll
    for (int i = 0; i < 8; i++)
#pragma unroll
        for (int j = 0; j < 4; j++) acc[i][j] = 0ull;

    for (int k0 = 0; k0 < Dq; k0 += 8) {
        float4 av = *(const float4*)&x[(size_t)(m0 + ar) * Dq + k0 + kc];
        float4 bv = *(const float4*)&W[(size_t)(k0 + brk) * Dq + n0 + bc * 4];
        __syncthreads();
        As2[(kc + 0) * 128 + ar] = pk2(av.x, av.x);
        As2[(kc + 1) * 128 + ar] = pk2(av.y, av.y);
        As2[(kc + 2) * 128 + ar] = pk2(av.z, av.z);
        As2[(kc + 3) * 128 + ar] = pk2(av.w, av.w);
        Bs2[brk * 64 + bc * 2 + 0] = pk2(bv.x, bv.y);
        Bs2[brk * 64 + bc * 2 + 1] = pk2(bv.z, bv.w);
        __syncthreads();
#pragma unroll
        for (int k = 0; k < 8; k++) {
            ulonglong2 a01 = *(const ulonglong2*)&As2[k * 128 + ty * 8 + 0];
            ulonglong2 a23 = *(const ulonglong2*)&As2[k * 128 + ty * 8 + 2];
            ulonglong2 a45 = *(const ulonglong2*)&As2[k * 128 + ty * 8 + 4];
            ulonglong2 a67 = *(const ulonglong2*)&As2[k * 128 + ty * 8 + 6];
            ulonglong2 b01 = *(const ulonglong2*)&Bs2[k * 64 + tx * 4 + 0];
            ulonglong2 b23 = *(const ulonglong2*)&Bs2[k * 64 + tx * 4 + 2];
            ull a[8] = {a01.x, a01.y, a23.x, a23.y, a45.x, a45.y, a67.x, a67.y};
            ull b[4] = {b01.x, b01.y, b23.x, b23.y};
#pragma unroll
            for (int i = 0; i < 8; i++)
#pragma unroll
                for (int j = 0; j < 4; j++)
                    acc[i][j] = fma2(a[i], b[j], acc[i][j]);
        }
    }

    float bl[8];
#pragma unroll
    for (int j = 0; j < 8; j++) bl[j] = bias[n0 + tx * 8 + j];

#pragma unroll
    for (int i = 0; i < 8; i++) {
        int m = m0 + ty * 8 + i;
        int bb = m >> 9;
        int tt = m & 511;
        float r[8];
#pragma unroll
        for (int j = 0; j < 4; j++) upk2(acc[i][j], r[2 * j], r[2 * j + 1]);
#pragma unroll
        for (int j = 0; j < 8; j++) r[j] += bl[j];
        float* orow = out + (size_t)(tt * Bq + bb) * Dq + n0 + tx * 8;
        *(float4*)&orow[0] = make_float4(r[0], r[1], r[2], r[3]);
        *(float4*)&orow[4] = make_float4(r[4], r[5], r[6], r[7]);
    }
}

// ============================================================
// Phase 2: one kernel per time step. 128 CTAs x 1024 threads
// (32 warps/SM for latency coverage). CTA owns 8 columns.
// tau streamed via cp.async 4-buffer ring; thread (b, kc16)
// accumulates 8 k per chunk.
// ============================================================
__global__ __launch_bounds__(1024, 1) void step_kernel(
    const float* __restrict__ Wt,
    const float* __restrict__ log_thresh,
    float* __restrict__ out,
    int t)
{
    extern __shared__ char smem[];
    const uint32_t sb = su32(smem);

    const int tid  = threadIdx.x;
    const int n0   = blockIdx.x * 8;
    const int ping = t & 1;
    const int b    = tid & 63;
    const int kc   = tid >> 6;          // 0..15

    const float* tau_src = &g_tauT[(size_t)ping * Dq * Bq];

    // ---- G0: weights + xtau/mem rows + v + log_thresh ----
#pragma unroll
    for (int r = 0; r < 2; r++) {
        int idx = r * 1024 + tid;                // 0..2047
        int k = idx >> 1, h = idx & 1;
        cpa16(sb + OFF_W + idx * 16, &Wt[(size_t)(Dq + k) * Dq + n0 + h * 4]);
    }
    if (tid < 128) {
        int bb = tid >> 1, h = tid & 1;
        cpa16(sb + OFF_X + tid * 16, &g_xtau[(size_t)(t * Bq + bb) * Dq + n0 + h * 4]);
    } else if (tid < 256) {
        int u = tid - 128, bb = u >> 1, h = u & 1;
        cpa16(sb + OFF_M + u * 16, &g_mem[(size_t)(t * Bq + bb) * Dq + n0 + h * 4]);
    } else if (tid < 384) {
        int u = tid - 256;
        cpa16(sb + OFF_V + u * 16, &g_v[(size_t)n0 * Bq + u * 4]);
    } else if (tid < 386) {
        int u = tid - 384;
        cpa16(sb + OFF_LT + u * 16, &log_thresh[n0 + u * 4]);
    }
    CPA_COMMIT();
    // ---- G1..G3: chunks 0..2 ----
#pragma unroll
    for (int c = 0; c < 3; c++) {
#pragma unroll
        for (int r = 0; r < 2; r++) {
            int idx = r * 1024 + tid;
            cpa16(sb + OFF_TAU + c * 32768 + idx * 16,
                  tau_src + (size_t)c * 128 * Bq + idx * 4);
        }
        CPA_COMMIT();
    }

    // ---- pipelined dot loop: 8 chunks x 8 k per thread ----
    ull acc0 = 0, acc1 = 0, acc2 = 0, acc3 = 0;
#pragma unroll
    for (int c = 0; c < 8; c++) {
        CPA_WAIT2();
        __syncthreads();
        if (c + 3 < 8) {
            int cn = c + 3;
#pragma unroll
            for (int r = 0; r < 2; r++) {
                int idx = r * 1024 + tid;
                cpa16(sb + OFF_TAU + (cn & 3) * 32768 + idx * 16,
                      tau_src + (size_t)cn * 128 * Bq + idx * 4);
            }
        }
        CPA_COMMIT();                   // real or dummy (keeps wait arithmetic exact)

        const float* tb = (const float*)(smem + OFF_TAU + (c & 3) * 32768);
        const ull*   wp = (const ull*)(smem + OFF_W) + (size_t)(c * 128 + kc * 8) * 4;
#pragma unroll
        for (int kl = 0; kl < 8; kl++) {
            float tv = tb[(kc * 8 + kl) * 64 + b];
            ull a = pk2(tv, tv);
            ulonglong2 w01 = *(const ulonglong2*)&wp[kl * 4 + 0];
            ulonglong2 w23 = *(const ulonglong2*)&wp[kl * 4 + 2];
            acc0 = fma2(a, w01.x, acc0); acc1 = fma2(a, w01.y, acc1);
            acc2 = fma2(a, w23.x, acc2); acc3 = fma2(a, w23.y, acc3);
        }
    }

    // ---- store partials (reuse tau buf0; its chunk long consumed) ----
    __syncthreads();
    ull* pr = (ull*)(smem + OFF_TAU);   // [kc][b][4] = 16*64*4 ull = 32KB
    pr[(kc * 64 + b) * 4 + 0] = acc0;
    pr[(kc * 64 + b) * 4 + 1] = acc1;
    pr[(kc * 64 + b) * 4 + 2] = acc2;
    pr[(kc * 64 + b) * 4 + 3] = acc3;
    __syncthreads();

    // ---- reduce 16 partials per (b, colpair) ----
    float* sDot = (float*)(smem + OFF_DOT);
    if (tid < 256) {
        int bb = tid >> 2, cp = tid & 3;
        ull s = 0;
#pragma unroll
        for (int q = 0; q < 16; q++)
            s = add2(s, pr[(q * 64 + bb) * 4 + cp]);
        float lo, hi; upk2(s, lo, hi);
        sDot[bb * 8 + 2 * cp + 0] = lo;
        sDot[bb * 8 + 2 * cp + 1] = hi;
    }
    __syncthreads();

    // ---- elementwise dynamics (threads 0..63, one batch each) ----
    if (tid < 64) {
        const int bb = tid;
        const float* sX  = (const float*)(smem + OFF_X);
        const float* sM  = (const float*)(smem + OFF_M);
        const float* sV  = (const float*)(smem + OFF_V);
        const float* sLT = (const float*)(smem + OFF_LT);

        float tauv[8], sp[8], vv[8];
#pragma unroll
        for (int j = 0; j < 8; j++) {
            float dot = sDot[bb * 8 + j];
            float xv  = sX[bb * 8 + j];
            float mv  = sM[bb * 8 + j];
            float th  = sigm(sLT[j]);
            vv[j] = sV[j * 64 + bb];
            tauv[j] = sigm(xv + dot);
            float alpha = expf(-1.0f / (tauv[j] + 1e-6f));
            float vn = alpha * vv[j] + (1.0f - alpha) * mv;
            float s = (vn >= th) ? 1.0f : 0.0f;
            vv[j] = vn * (1.0f - s);
            sp[j] = s;
        }

        // spikes [B][T][D]
        float* srow = out + (size_t)(bb * Tq + t) * Dq + n0;
        *(float4*)&srow[0] = make_float4(sp[0], sp[1], sp[2], sp[3]);
        *(float4*)&srow[4] = make_float4(sp[4], sp[5], sp[6], sp[7]);

        // tau -> pong buffer (transposed, coalesced), v -> g_v
        float* tdst = &g_tauT[(size_t)(ping ^ 1) * Dq * Bq];
#pragma unroll
        for (int j = 0; j < 8; j++) {
            tdst[(size_t)(n0 + j) * Bq + bb] = tauv[j];
            g_v [(size_t)(n0 + j) * Bq + bb] = vv[j];
        }

        if (t == Tq - 1) {
            float* tout = out + (size_t)Mq * Dq + bb * Dq + n0;
            *(float4*)&tout[0] = make_float4(tauv[0], tauv[1], tauv[2], tauv[3]);
            *(float4*)&tout[4] = make_float4(tauv[4], tauv[5], tauv[6], tauv[7]);
            float* vout = out + (size_t)Mq * Dq + Bq * Dq + bb * Dq + n0;
            *(float4*)&vout[0] = make_float4(vv[0], vv[1], vv[2], vv[3]);
            *(float4*)&vout[4] = make_float4(vv[4], vv[5], vv[6], vv[7]);
        }
    }
}

// ============================================================
extern "C" void kernel_launch(void* const* d_in, const int* in_sizes, int n_in,
                              void* d_out, int out_size)
{
    const float* x  = (const float*)d_in[0];
    const float* Wt = (const float*)d_in[1];
    const float* bt = (const float*)d_in[2];
    const float* Wm = (const float*)d_in[3];
    const float* bm = (const float*)d_in[4];
    const float* lt = (const float*)d_in[5];
    float* out = (float*)d_out;

    cudaFuncSetAttribute(step_kernel,
                         cudaFuncAttributeMaxDynamicSharedMemorySize, SMEM_BYTES);

    init_kernel<<<256, 256>>>(lt, out);

    dim3 ggrid(Dq / 128, Mq / 128, 2);
    gemm_kernel<<<ggrid, 256>>>(x, Wt, bt, Wm, bm);

    for (int t = 0; t < Tq; t++)
        step_kernel<<<128, 1024, SMEM_BYTES>>>(Wt, lt, out, t);
}

// round 12
// speedup vs baseline: 1.1179x; 1.1179x over previous
#include <cuda_runtime.h>
#include <cstdint>

#define Bq 64
#define Tq 512
#define Dq 1024
#define Mq (Bq*Tq)

// ---- scratch (device globals: allocation-free) ----
__device__ float g_xtau[Tq*Bq*Dq];   // [t][b][d]
__device__ float g_mem [Tq*Bq*Dq];   // [t][b][d]
__device__ float g_tauT[2*Dq*Bq];    // ping-pong, TRANSPOSED [p][d][b]
__device__ float g_v   [Dq*Bq];      // TRANSPOSED [d][b]

typedef unsigned long long ull;

__device__ __forceinline__ ull pk2(float lo, float hi) {
    ull r; asm("mov.b64 %0, {%1,%2};" : "=l"(r) : "f"(lo), "f"(hi)); return r;
}
__device__ __forceinline__ void upk2(ull a, float& lo, float& hi) {
    asm("mov.b64 {%0,%1}, %2;" : "=f"(lo), "=f"(hi) : "l"(a));
}
__device__ __forceinline__ ull fma2(ull a, ull b, ull c) {
    ull d; asm("fma.rn.f32x2 %0, %1, %2, %3;" : "=l"(d) : "l"(a), "l"(b), "l"(c)); return d;
}
__device__ __forceinline__ ull add2(ull a, ull b) {
    ull d; asm("add.rn.f32x2 %0, %1, %2;" : "=l"(d) : "l"(a), "l"(b)); return d;
}
__device__ __forceinline__ float sigm(float x) { return 1.0f / (1.0f + expf(-x)); }

// ============================================================
// Init: tau ping buffer = 1, v = 0, thresh output
// ============================================================
__global__ void init_kernel(const float* __restrict__ log_thresh,
                            float* __restrict__ out)
{
    int i = blockIdx.x * blockDim.x + threadIdx.x;
    if (i < Dq * Bq) {
        g_tauT[i] = 1.0f;
        g_v[i]    = 0.0f;
    }
    if (i < Dq)
        out[(size_t)Mq * Dq + 2 * Bq * Dq + i] = sigm(log_thresh[i]);
}

// ============================================================
// Phase 1: big GEMMs (at FFMA2 issue floor; unchanged)
// ============================================================
__global__ __launch_bounds__(256, 1) void gemm_kernel(
    const float* __restrict__ x,
    const float* __restrict__ Wt, const float* __restrict__ bt,
    const float* __restrict__ Wm, const float* __restrict__ bm)
{
    const int z = blockIdx.z;
    const float* __restrict__ W    = z ? Wm : Wt;
    const float* __restrict__ bias = z ? bm : bt;
    float* __restrict__ out        = z ? g_mem : g_xtau;

    __shared__ ull As2[8 * 128];
    __shared__ ull Bs2[8 * 64];

    const int tid = threadIdx.x;
    const int tx = tid & 15, ty = tid >> 4;
    const int m0 = blockIdx.y * 128;
    const int n0 = blockIdx.x * 128;

    const int ar  = tid >> 1;
    const int kc  = (tid & 1) * 4;
    const int brk = tid >> 5;
    const int bc  = tid & 31;

    ull acc[8][4];
#pragma unroll
    for (int i = 0; i < 8; i++)
#pragma unroll
        for (int j = 0; j < 4; j++) acc[i][j] = 0ull;

    for (int k0 = 0; k0 < Dq; k0 += 8) {
        float4 av = *(const float4*)&x[(size_t)(m0 + ar) * Dq + k0 + kc];
        float4 bv = *(const float4*)&W[(size_t)(k0 + brk) * Dq + n0 + bc * 4];
        __syncthreads();
        As2[(kc + 0) * 128 + ar] = pk2(av.x, av.x);
        As2[(kc + 1) * 128 + ar] = pk2(av.y, av.y);
        As2[(kc + 2) * 128 + ar] = pk2(av.z, av.z);
        As2[(kc + 3) * 128 + ar] = pk2(av.w, av.w);
        Bs2[brk * 64 + bc * 2 + 0] = pk2(bv.x, bv.y);
        Bs2[brk * 64 + bc * 2 + 1] = pk2(bv.z, bv.w);
        __syncthreads();
#pragma unroll
        for (int k = 0; k < 8; k++) {
            ulonglong2 a01 = *(const ulonglong2*)&As2[k * 128 + ty * 8 + 0];
            ulonglong2 a23 = *(const ulonglong2*)&As2[k * 128 + ty * 8 + 2];
            ulonglong2 a45 = *(const ulonglong2*)&As2[k * 128 + ty * 8 + 4];
            ulonglong2 a67 = *(const ulonglong2*)&As2[k * 128 + ty * 8 + 6];
            ulonglong2 b01 = *(const ulonglong2*)&Bs2[k * 64 + tx * 4 + 0];
            ulonglong2 b23 = *(const ulonglong2*)&Bs2[k * 64 + tx * 4 + 2];
            ull a[8] = {a01.x, a01.y, a23.x, a23.y, a45.x, a45.y, a67.x, a67.y};
            ull b[4] = {b01.x, b01.y, b23.x, b23.y};
#pragma unroll
            for (int i = 0; i < 8; i++)
#pragma unroll
                for (int j = 0; j < 4; j++)
                    acc[i][j] = fma2(a[i], b[j], acc[i][j]);
        }
    }

    float bl[8];
#pragma unroll
    for (int j = 0; j < 8; j++) bl[j] = bias[n0 + tx * 8 + j];

#pragma unroll
    for (int i = 0; i < 8; i++) {
        int m = m0 + ty * 8 + i;
        int bb = m >> 9;
        int tt = m & 511;
        float r[8];
#pragma unroll
        for (int j = 0; j < 4; j++) upk2(acc[i][j], r[2 * j], r[2 * j + 1]);
#pragma unroll
        for (int j = 0; j < 8; j++) r[j] += bl[j];
        float* orow = out + (size_t)(tt * Bq + bb) * Dq + n0 + tx * 8;
        *(float4*)&orow[0] = make_float4(r[0], r[1], r[2], r[3]);
        *(float4*)&orow[4] = make_float4(r[4], r[5], r[6], r[7]);
    }
}

// ============================================================
// Phase 2: one kernel per time step. 128 CTAs x 512 threads.
// CTA owns 8 columns. NO smem staging: tau has zero intra-CTA
// reuse (direct coalesced LDG.64), weights are warp-uniform
// (direct broadcast LDG.128). Thread (bp, kc) owns b = {2bp,
// 2bp+1}, k in [kc*64, kc*64+64).
// ============================================================
__global__ __launch_bounds__(512, 1) void step_kernel(
    const float* __restrict__ Wt,
    const float* __restrict__ log_thresh,
    float* __restrict__ out,
    int t)
{
    __shared__ ull   sRed[16][32][9];   // 36.9KB [kc][bp][8 accs + pad]
    __shared__ float sDot[64 * 8];      // 2KB reduced dots [b][8]

    const int tid  = threadIdx.x;
    const int n0   = blockIdx.x * 8;
    const int ping = t & 1;
    const int bp   = tid & 31;          // b-pair 0..31
    const int kc   = tid >> 5;          // 0..15

    // ---- dot: k in [kc*64, kc*64+64), b = 2bp, 2bp+1 ----
    const float2* __restrict__ tau2 = (const float2*)
        (&g_tauT[(size_t)ping * Dq * Bq]) + (size_t)(kc * 64) * 32 + bp;
    const float* __restrict__ wrow = &Wt[(size_t)(Dq + kc * 64) * Dq + n0];

    ull a0_0 = 0, a0_1 = 0, a0_2 = 0, a0_3 = 0;   // b = 2bp
    ull a1_0 = 0, a1_1 = 0, a1_2 = 0, a1_3 = 0;   // b = 2bp+1
#pragma unroll 16
    for (int kk = 0; kk < 64; kk++) {
        float2 tv = __ldcg(tau2 + (size_t)kk * 32);
        ulonglong2 w01 = __ldg((const ulonglong2*)(wrow + (size_t)kk * Dq));
        ulonglong2 w23 = __ldg((const ulonglong2*)(wrow + (size_t)kk * Dq + 4));
        ull a = pk2(tv.x, tv.x);
        a0_0 = fma2(a, w01.x, a0_0); a0_1 = fma2(a, w01.y, a0_1);
        a0_2 = fma2(a, w23.x, a0_2); a0_3 = fma2(a, w23.y, a0_3);
        a = pk2(tv.y, tv.y);
        a1_0 = fma2(a, w01.x, a1_0); a1_1 = fma2(a, w01.y, a1_1);
        a1_2 = fma2(a, w23.x, a1_2); a1_3 = fma2(a, w23.y, a1_3);
    }

    // ---- store partials (padded rows -> low bank conflict) ----
    ull* pr = &sRed[kc][bp][0];
    pr[0] = a0_0; pr[1] = a0_1; pr[2] = a0_2; pr[3] = a0_3;
    pr[4] = a1_0; pr[5] = a1_1; pr[6] = a1_2; pr[7] = a1_3;
    __syncthreads();

    // ---- dynamics-input prefetch (overlaps the reduce below) ----
    float4 x0, x1, m0, m1;
    float vv[8], lt[8];
    if (tid < 64) {
        const float* xr = &g_xtau[(size_t)(t * Bq + tid) * Dq + n0];
        const float* mr = &g_mem [(size_t)(t * Bq + tid) * Dq + n0];
        x0 = __ldcg((const float4*)&xr[0]); x1 = __ldcg((const float4*)&xr[4]);
        m0 = __ldcg((const float4*)&mr[0]); m1 = __ldcg((const float4*)&mr[4]);
#pragma unroll
        for (int j = 0; j < 8; j++) {
            vv[j] = __ldcg(&g_v[(size_t)(n0 + j) * Bq + tid]);
            lt[j] = __ldg(&log_thresh[n0 + j]);
        }
    }

    // ---- reduce 16 kc-partials per (b, colpair) ----
    if (tid < 256) {
        int bb = tid >> 2, cp = tid & 3;
        int bpp = bb >> 1, half = (bb & 1) * 4;
        ull s = 0;
#pragma unroll
        for (int q = 0; q < 16; q++)
            s = add2(s, sRed[q][bpp][half + cp]);
        float lo, hi; upk2(s, lo, hi);
        sDot[bb * 8 + 2 * cp + 0] = lo;
        sDot[bb * 8 + 2 * cp + 1] = hi;
    }
    __syncthreads();

    // ---- elementwise dynamics (threads 0..63, one batch each) ----
    if (tid < 64) {
        const int bb = tid;
        float xv[8] = {x0.x, x0.y, x0.z, x0.w, x1.x, x1.y, x1.z, x1.w};
        float mv[8] = {m0.x, m0.y, m0.z, m0.w, m1.x, m1.y, m1.z, m1.w};

        float tauv[8], sp[8];
#pragma unroll
        for (int j = 0; j < 8; j++) {
            float dot = sDot[bb * 8 + j];
            float th  = sigm(lt[j]);
            tauv[j] = sigm(xv[j] + dot);
            float alpha = expf(-1.0f / (tauv[j] + 1e-6f));
            float vn = alpha * vv[j] + (1.0f - alpha) * mv[j];
            float s = (vn >= th) ? 1.0f : 0.0f;
            vv[j] = vn * (1.0f - s);
            sp[j] = s;
        }

        // spikes [B][T][D]
        float* srow = out + (size_t)(bb * Tq + t) * Dq + n0;
        *(float4*)&srow[0] = make_float4(sp[0], sp[1], sp[2], sp[3]);
        *(float4*)&srow[4] = make_float4(sp[4], sp[5], sp[6], sp[7]);

        // tau -> pong buffer (transposed), v -> g_v
        float* tdst = &g_tauT[(size_t)(ping ^ 1) * Dq * Bq];
#pragma unroll
        for (int j = 0; j < 8; j++) {
            tdst[(size_t)(n0 + j) * Bq + bb] = tauv[j];
            g_v [(size_t)(n0 + j) * Bq + bb] = vv[j];
        }

        if (t == Tq - 1) {
            float* tout = out + (size_t)Mq * Dq + bb * Dq + n0;
            *(float4*)&tout[0] = make_float4(tauv[0], tauv[1], tauv[2], tauv[3]);
            *(float4*)&tout[4] = make_float4(tauv[4], tauv[5], tauv[6], tauv[7]);
            float* vout = out + (size_t)Mq * Dq + Bq * Dq + bb * Dq + n0;
            *(float4*)&vout[0] = make_float4(vv[0], vv[1], vv[2], vv[3]);
            *(float4*)&vout[4] = make_float4(vv[4], vv[5], vv[6], vv[7]);
        }
    }
}

// ============================================================
extern "C" void kernel_launch(void* const* d_in, const int* in_sizes, int n_in,
                              void* d_out, int out_size)
{
    const float* x  = (const float*)d_in[0];
    const float* Wt = (const float*)d_in[1];
    const float* bt = (const float*)d_in[2];
    const float* Wm = (const float*)d_in[3];
    const float* bm = (const float*)d_in[4];
    const float* lt = (const float*)d_in[5];
    float* out = (float*)d_out;

    init_kernel<<<256, 256>>>(lt, out);

    dim3 ggrid(Dq / 128, Mq / 128, 2);
    gemm_kernel<<<ggrid, 256>>>(x, Wt, bt, Wm, bm);

    for (int t = 0; t < Tq; t++)
        step_kernel<<<128, 512>>>(Wt, lt, out, t);
}

// round 14
// speedup vs baseline: 1.2949x; 1.1584x over previous
#include <cuda_runtime.h>
#include <cstdint>

#define Bq 64
#define Tq 512
#define Dq 1024
#define Mq (Bq*Tq)

// ---- scratch (device globals: allocation-free) ----
__device__ float g_xtau[Tq*Bq*Dq];   // [t][b][d]
__device__ float g_mem [Tq*Bq*Dq];   // [t][b][d]
__device__ float g_tauT[2*Dq*Bq];    // ping-pong, TRANSPOSED [p][d][b]
__device__ unsigned g_count = 0;
__device__ unsigned g_epoch = 0;

typedef unsigned long long ull;

__device__ __forceinline__ ull pk2(float lo, float hi) {
    ull r; asm("mov.b64 %0, {%1,%2};" : "=l"(r) : "f"(lo), "f"(hi)); return r;
}
__device__ __forceinline__ void upk2(ull a, float& lo, float& hi) {
    asm("mov.b64 {%0,%1}, %2;" : "=f"(lo), "=f"(hi) : "l"(a));
}
__device__ __forceinline__ ull fma2(ull a, ull b, ull c) {
    ull d; asm("fma.rn.f32x2 %0, %1, %2, %3;" : "=l"(d) : "l"(a), "l"(b), "l"(c)); return d;
}
__device__ __forceinline__ ull add2(ull a, ull b) {
    ull d; asm("add.rn.f32x2 %0, %1, %2;" : "=l"(d) : "l"(a), "l"(b)); return d;
}
__device__ __forceinline__ float sigm(float x) { return 1.0f / (1.0f + expf(-x)); }

__device__ __forceinline__ unsigned ld_acq(unsigned* p) {
    unsigned v; asm volatile("ld.acquire.gpu.u32 %0, [%1];" : "=r"(v) : "l"(p) : "memory");
    return v;
}
__device__ __forceinline__ void st_rel(unsigned* p, unsigned v) {
    asm volatile("st.release.gpu.u32 [%0], %1;" :: "l"(p), "r"(v) : "memory");
}

// ============================================================
// Grid barrier: sense-reversing, bounded spin (hang -> finite
// wrong answer instead of dead container).
// ============================================================
__device__ __forceinline__ void gbar(unsigned nctas, bool wrote) {
    if (wrote) __threadfence();
    __syncthreads();
    if (threadIdx.x == 0) {
        unsigned e = ld_acq(&g_epoch);
        if (atomicAdd(&g_count, 1) == nctas - 1) {
            g_count = 0;
            st_rel(&g_epoch, e + 1);
        } else {
            unsigned guard = 0;
            while (ld_acq(&g_epoch) == e) {
                if (++guard > (1u << 20)) break;   // ~130ms escape hatch
                __nanosleep(32);
            }
        }
    }
    __syncthreads();
}

// ============================================================
// Phase 1: big GEMMs (at FFMA2 issue floor; unchanged)
// ============================================================
__global__ __launch_bounds__(256, 1) void gemm_kernel(
    const float* __restrict__ x,
    const float* __restrict__ Wt, const float* __restrict__ bt,
    const float* __restrict__ Wm, const float* __restrict__ bm)
{
    const int z = blockIdx.z;
    const float* __restrict__ W    = z ? Wm : Wt;
    const float* __restrict__ bias = z ? bm : bt;
    float* __restrict__ out        = z ? g_mem : g_xtau;

    __shared__ ull As2[8 * 128];
    __shared__ ull Bs2[8 * 64];

    const int tid = threadIdx.x;
    const int tx = tid & 15, ty = tid >> 4;
    const int m0 = blockIdx.y * 128;
    const int n0 = blockIdx.x * 128;

    const int ar  = tid >> 1;
    const int kc  = (tid & 1) * 4;
    const int brk = tid >> 5;
    const int bc  = tid & 31;

    ull acc[8][4];
#pragma unroll
    for (int i = 0; i < 8; i++)
#pragma unroll
        for (int j = 0; j < 4; j++) acc[i][j] = 0ull;

    for (int k0 = 0; k0 < Dq; k0 += 8) {
        float4 av = *(const float4*)&x[(size_t)(m0 + ar) * Dq + k0 + kc];
        float4 bv = *(const float4*)&W[(size_t)(k0 + brk) * Dq + n0 + bc * 4];
        __syncthreads();
        As2[(kc + 0) * 128 + ar] = pk2(av.x, av.x);
        As2[(kc + 1) * 128 + ar] = pk2(av.y, av.y);
        As2[(kc + 2) * 128 + ar] = pk2(av.z, av.z);
        As2[(kc + 3) * 128 + ar] = pk2(av.w, av.w);
        Bs2[brk * 64 + bc * 2 + 0] = pk2(bv.x, bv.y);
        Bs2[brk * 64 + bc * 2 + 1] = pk2(bv.z, bv.w);
        __syncthreads();
#pragma unroll
        for (int k = 0; k < 8; k++) {
            ulonglong2 a01 = *(const ulonglong2*)&As2[k * 128 + ty * 8 + 0];
            ulonglong2 a23 = *(const ulonglong2*)&As2[k * 128 + ty * 8 + 2];
            ulonglong2 a45 = *(const ulonglong2*)&As2[k * 128 + ty * 8 + 4];
            ulonglong2 a67 = *(const ulonglong2*)&As2[k * 128 + ty * 8 + 6];
            ulonglong2 b01 = *(const ulonglong2*)&Bs2[k * 64 + tx * 4 + 0];
            ulonglong2 b23 = *(const ulonglong2*)&Bs2[k * 64 + tx * 4 + 2];
            ull a[8] = {a01.x, a01.y, a23.x, a23.y, a45.x, a45.y, a67.x, a67.y};
            ull b[4] = {b01.x, b01.y, b23.x, b23.y};
#pragma unroll
            for (int i = 0; i < 8; i++)
#pragma unroll
                for (int j = 0; j < 4; j++)
                    acc[i][j] = fma2(a[i], b[j], acc[i][j]);
        }
    }

    float bl[8];
#pragma unroll
    for (int j = 0; j < 8; j++) bl[j] = bias[n0 + tx * 8 + j];

#pragma unroll
    for (int i = 0; i < 8; i++) {
        int m = m0 + ty * 8 + i;
        int bb = m >> 9;
        int tt = m & 511;
        float r[8];
#pragma unroll
        for (int j = 0; j < 4; j++) upk2(acc[i][j], r[2 * j], r[2 * j + 1]);
#pragma unroll
        for (int j = 0; j < 8; j++) r[j] += bl[j];
        float* orow = out + (size_t)(tt * Bq + bb) * Dq + n0 + tx * 8;
        *(float4*)&orow[0] = make_float4(r[0], r[1], r[2], r[3]);
        *(float4*)&orow[4] = make_float4(r[4], r[5], r[6], r[7]);
    }
}

// ---- dynamic smem layout for scan ----
#define OFF_W    0                       // 32KB  weights [k][4 ull colpairs]
#define OFF_RED  32768                   // 36.9KB [kc][bp][9] padded partials
#define OFF_DOT  (32768 + 36864)         // 2KB reduced dots [b][8]
#define SCAN_SMEM (OFF_DOT + 2048)       // 71680 B

// ============================================================
// Phase 2: PERSISTENT scan. 128 CTAs x 512 threads, all 512
// steps in one kernel. CTA owns 8 columns; weight slice lives
// in smem the whole time; v/thresh live in registers. Grid
// barrier between steps (bounded spin).
// ============================================================
__global__ __launch_bounds__(512, 1) void scan_kernel(
    const float* __restrict__ Wt,
    const float* __restrict__ log_thresh,
    float* __restrict__ out)
{
    extern __shared__ char smem[];
    ull* sW = (ull*)(smem + OFF_W);
    ull (*sRed)[32][9] = (ull(*)[32][9])(smem + OFF_RED);
    float* sDot = (float*)(smem + OFF_DOT);

    const int tid = threadIdx.x;
    const int n0  = blockIdx.x * 8;
    const int bp  = tid & 31;           // b-pair 0..31
    const int kc  = tid >> 5;           // 0..15

    // ---- one-time: weight slice Wt_tau[:, n0:n0+8] -> smem ----
#pragma unroll
    for (int r = 0; r < 4; r++) {
        int idx = r * 512 + tid;        // 0..2047
        int k = idx >> 1, h = idx & 1;
        float4 w = __ldg((const float4*)&Wt[(size_t)(Dq + k) * Dq + n0 + h * 4]);
        sW[k * 4 + h * 2 + 0] = pk2(w.x, w.y);
        sW[k * 4 + h * 2 + 1] = pk2(w.z, w.w);
    }

    // ---- one-time: v regs, thresh regs, tau ping init ----
    float vv[8], th[8];
    if (tid < 64) {
#pragma unroll
        for (int j = 0; j < 8; j++) {
            vv[j] = 0.0f;
            th[j] = sigm(__ldg(&log_thresh[n0 + j]));
            g_tauT[(size_t)(n0 + j) * Bq + tid] = 1.0f;
        }
    }
    if (tid == 0) {
#pragma unroll
        for (int j = 0; j < 8; j++)
            out[(size_t)Mq * Dq + 2 * Bq * Dq + n0 + j] = sigm(__ldg(&log_thresh[n0 + j]));
    }
    gbar(gridDim.x, tid < 64);

    for (int t = 0; t < Tq; t++) {
        const int ping = t & 1;

        // ---- prefetch dynamics inputs (overlaps dot) ----
        float4 x0, x1, m0, m1;
        if (tid < 64) {
            const float* xr = &g_xtau[(size_t)(t * Bq + tid) * Dq + n0];
            const float* mr = &g_mem [(size_t)(t * Bq + tid) * Dq + n0];
            x0 = __ldcg((const float4*)&xr[0]); x1 = __ldcg((const float4*)&xr[4]);
            m0 = __ldcg((const float4*)&mr[0]); m1 = __ldcg((const float4*)&mr[4]);
        }

        // ---- dot: k in [kc*64, kc*64+64), b = {2bp, 2bp+1} ----
        const float2* __restrict__ tau2 = (const float2*)
            (&g_tauT[(size_t)ping * Dq * Bq]) + (size_t)(kc * 64) * 32 + bp;
        const ull* __restrict__ wp = &sW[(size_t)(kc * 64) * 4];

        ull a0_0 = 0, a0_1 = 0, a0_2 = 0, a0_3 = 0;
        ull a1_0 = 0, a1_1 = 0, a1_2 = 0, a1_3 = 0;
#pragma unroll 16
        for (int kk = 0; kk < 64; kk++) {
            float2 tv = __ldcg(tau2 + (size_t)kk * 32);
            ulonglong2 w01 = *(const ulonglong2*)&wp[kk * 4 + 0];   // broadcast LDS
            ulonglong2 w23 = *(const ulonglong2*)&wp[kk * 4 + 2];
            ull a = pk2(tv.x, tv.x);
            a0_0 = fma2(a, w01.x, a0_0); a0_1 = fma2(a, w01.y, a0_1);
            a0_2 = fma2(a, w23.x, a0_2); a0_3 = fma2(a, w23.y, a0_3);
            a = pk2(tv.y, tv.y);
            a1_0 = fma2(a, w01.x, a1_0); a1_1 = fma2(a, w01.y, a1_1);
            a1_2 = fma2(a, w23.x, a1_2); a1_3 = fma2(a, w23.y, a1_3);
        }

        ull* pr = &sRed[kc][bp][0];
        pr[0] = a0_0; pr[1] = a0_1; pr[2] = a0_2; pr[3] = a0_3;
        pr[4] = a1_0; pr[5] = a1_1; pr[6] = a1_2; pr[7] = a1_3;
        __syncthreads();

        // ---- reduce 16 kc-partials per (b, colpair) ----
        if (tid < 256) {
            int bb = tid >> 2, cp = tid & 3;
            int bpp = bb >> 1, half = (bb & 1) * 4;
            ull s = 0;
#pragma unroll
            for (int q = 0; q < 16; q++)
                s = add2(s, sRed[q][bpp][half + cp]);
            float lo, hi; upk2(s, lo, hi);
            sDot[bb * 8 + 2 * cp + 0] = lo;
            sDot[bb * 8 + 2 * cp + 1] = hi;
        }
        __syncthreads();

        // ---- dynamics (threads 0..63, one batch each) ----
        if (tid < 64) {
            const int bb = tid;
            float xv[8] = {x0.x, x0.y, x0.z, x0.w, x1.x, x1.y, x1.z, x1.w};
            float mv[8] = {m0.x, m0.y, m0.z, m0.w, m1.x, m1.y, m1.z, m1.w};

            float tauv[8], sp[8];
#pragma unroll
            for (int j = 0; j < 8; j++) {
                tauv[j] = sigm(xv[j] + sDot[bb * 8 + j]);
                float alpha = expf(-1.0f / (tauv[j] + 1e-6f));
                float vn = alpha * vv[j] + (1.0f - alpha) * mv[j];
                float s = (vn >= th[j]) ? 1.0f : 0.0f;
                vv[j] = vn * (1.0f - s);
                sp[j] = s;
            }

            float* srow = out + (size_t)(bb * Tq + t) * Dq + n0;
            *(float4*)&srow[0] = make_float4(sp[0], sp[1], sp[2], sp[3]);
            *(float4*)&srow[4] = make_float4(sp[4], sp[5], sp[6], sp[7]);

            float* tdst = &g_tauT[(size_t)(ping ^ 1) * Dq * Bq];
#pragma unroll
            for (int j = 0; j < 8; j++)
                tdst[(size_t)(n0 + j) * Bq + bb] = tauv[j];

            if (t == Tq - 1) {
                float* tout = out + (size_t)Mq * Dq + bb * Dq + n0;
                *(float4*)&tout[0] = make_float4(tauv[0], tauv[1], tauv[2], tauv[3]);
                *(float4*)&tout[4] = make_float4(tauv[4], tauv[5], tauv[6], tauv[7]);
                float* vout = out + (size_t)Mq * Dq + Bq * Dq + bb * Dq + n0;
                *(float4*)&vout[0] = make_float4(vv[0], vv[1], vv[2], vv[3]);
                *(float4*)&vout[4] = make_float4(vv[4], vv[5], vv[6], vv[7]);
            }
        }
        gbar(gridDim.x, tid < 64);
    }
}

// ============================================================
extern "C" void kernel_launch(void* const* d_in, const int* in_sizes, int n_in,
                              void* d_out, int out_size)
{
    const float* x  = (const float*)d_in[0];
    const float* Wt = (const float*)d_in[1];
    const float* bt = (const float*)d_in[2];
    const float* Wm = (const float*)d_in[3];
    const float* bm = (const float*)d_in[4];
    const float* lt = (const float*)d_in[5];
    float* out = (float*)d_out;

    cudaFuncSetAttribute(scan_kernel,
                         cudaFuncAttributeMaxDynamicSharedMemorySize, SCAN_SMEM);

    dim3 ggrid(Dq / 128, Mq / 128, 2);
    gemm_kernel<<<ggrid, 256>>>(x, Wt, bt, Wm, bm);

    scan_kernel<<<128, 512, SCAN_SMEM>>>(Wt, lt, out);
}